// round 9
// baseline (speedup 1.0000x reference)
#include <cuda_runtime.h>
#include <cstdint>

#define N_NODES 100000
#define N_EDGES 1000000
#define SCAN_B 1024
#define NBLK ((N_NODES + SCAN_B - 1) / SCAN_B)   // 98
#define GBLK ((N_NODES + 63) / 64)               // 1563 (64-node gemm tiles)

// ---------------- device scratch (static, allocation-free) ----------------
__device__ int   g_cnt[N_NODES];
__device__ int   g_rowstart[N_NODES + 1];
__device__ int   g_cursor[N_NODES];
__device__ float g_recip[N_NODES];
__device__ int   g_srcs[N_EDGES];
__device__ int   g_bsum[NBLK];
__device__ int   g_boff[NBLK];
__device__ float g_XW[(size_t)N_NODES * 128];  // [A=x@W1l | B=x@W1r]
__device__ float g_h [(size_t)N_NODES * 64];   // layer-1 output
__device__ float g_HW[(size_t)N_NODES * 64];   // [C=h@W2l | D=h@W2r]
__device__ int   g_is64;

typedef unsigned long long ull;

__device__ __forceinline__ void ffma2(ull& d, ull a, ull b) {
    asm("fma.rn.f32x2 %0, %1, %2, %0;" : "+l"(d) : "l"(a), "l"(b));
}
__device__ __forceinline__ float hadd2(ull v) {
    float lo, hi;
    asm("mov.b64 {%0, %1}, %2;" : "=f"(lo), "=f"(hi) : "l"(v));
    return lo + hi;
}

// ---------------- dtype detection: int64 vs int32 edge_index ----------------
__global__ void k_detect(const int* __restrict__ ei) {
    if (threadIdx.x == 0 && blockIdx.x == 0) {
        int odd_nonzero = 0;
        for (int i = 0; i < 64; i++)
            if (ei[2 * i + 1] != 0) odd_nonzero++;
        // int64 data: high 32-bit words (odd int32 slots) are all zero.
        g_is64 = (odd_nonzero == 0) ? 1 : 0;
    }
}

__global__ void k_zero_cnt() {
    int i = blockIdx.x * blockDim.x + threadIdx.x;
    if (i < N_NODES) g_cnt[i] = 0;
}

// Vectorized histogram over the dst half of edge_index.
__global__ void k_hist(const void* __restrict__ eiv) {
    int is64 = g_is64;
    int stride = gridDim.x * blockDim.x;
    int tid = blockIdx.x * blockDim.x + threadIdx.x;
    if (is64) {
        const longlong2* dst = (const longlong2*)(((const long long*)eiv) + N_EDGES);
        for (int e = tid; e < N_EDGES / 2; e += stride) {
            longlong2 v = dst[e];
            atomicAdd(&g_cnt[(int)v.x], 1);
            atomicAdd(&g_cnt[(int)v.y], 1);
        }
    } else {
        const int4* dst = (const int4*)(((const int*)eiv) + N_EDGES);
        for (int e = tid; e < N_EDGES / 4; e += stride) {
            int4 v = dst[e];
            atomicAdd(&g_cnt[v.x], 1);
            atomicAdd(&g_cnt[v.y], 1);
            atomicAdd(&g_cnt[v.z], 1);
            atomicAdd(&g_cnt[v.w], 1);
        }
    }
}

// ---------------- hierarchical exclusive scan of g_cnt ----------------
__global__ void __launch_bounds__(SCAN_B) k_scan1() {
    __shared__ int sh[SCAN_B];
    int tid = threadIdx.x;
    int j = blockIdx.x * SCAN_B + tid;
    int c = (j < N_NODES) ? g_cnt[j] : 0;
    int v = c;
    sh[tid] = v;
    __syncthreads();
    #pragma unroll
    for (int off = 1; off < SCAN_B; off <<= 1) {
        int t = (tid >= off) ? sh[tid - off] : 0;
        __syncthreads();
        v += t;
        sh[tid] = v;
        __syncthreads();
    }
    if (j < N_NODES) g_rowstart[j] = v - c;   // local exclusive
    if (tid == SCAN_B - 1) g_bsum[blockIdx.x] = v;
}

__global__ void k_scan2() {
    __shared__ int sh[128];
    int tid = threadIdx.x;
    int c = (tid < NBLK) ? g_bsum[tid] : 0;
    int v = c;
    sh[tid] = v;
    __syncthreads();
    #pragma unroll
    for (int off = 1; off < 128; off <<= 1) {
        int t = (tid >= off) ? sh[tid - off] : 0;
        __syncthreads();
        v += t;
        sh[tid] = v;
        __syncthreads();
    }
    if (tid < NBLK) g_boff[tid] = v - c;      // exclusive block offset
}

__global__ void k_scan3() {
    int j = blockIdx.x * blockDim.x + threadIdx.x;
    if (j < N_NODES) {
        int rs = g_rowstart[j] + g_boff[j >> 10];
        g_rowstart[j] = rs;
        g_cursor[j]   = rs;
        int c = g_cnt[j];
        g_recip[j] = 1.0f / (float)(c > 0 ? c : 1);
    }
    if (j == 0) g_rowstart[N_NODES] = N_EDGES;  // grand total is static
}

__global__ void k_scatter(const void* __restrict__ eiv) {
    int is64 = g_is64;
    int stride = gridDim.x * blockDim.x;
    int tid = blockIdx.x * blockDim.x + threadIdx.x;
    if (is64) {
        const long long* src = (const long long*)eiv;
        const longlong2* dst = (const longlong2*)(src + N_EDGES);
        const longlong2* src2 = (const longlong2*)src;
        for (int e = tid; e < N_EDGES / 2; e += stride) {
            longlong2 d = dst[e];
            longlong2 s = src2[e];
            int p0 = atomicAdd(&g_cursor[(int)d.x], 1);
            g_srcs[p0] = (int)s.x;
            int p1 = atomicAdd(&g_cursor[(int)d.y], 1);
            g_srcs[p1] = (int)s.y;
        }
    } else {
        const int* src = (const int*)eiv;
        const int4* dst = (const int4*)(src + N_EDGES);
        const int4* src4 = (const int4*)src;
        for (int e = tid; e < N_EDGES / 4; e += stride) {
            int4 d = dst[e];
            int4 s = src4[e];
            int p0 = atomicAdd(&g_cursor[d.x], 1); g_srcs[p0] = s.x;
            int p1 = atomicAdd(&g_cursor[d.y], 1); g_srcs[p1] = s.y;
            int p2 = atomicAdd(&g_cursor[d.z], 1); g_srcs[p2] = s.z;
            int p3 = atomicAdd(&g_cursor[d.w], 1); g_srcs[p3] = s.w;
        }
    }
}

// ---------------- GEMM1: XW[n][0:128] = x[n] @ [W1l | W1r] ----------------
// 64-node x 128-col block tile; 256 threads; per-thread 8-node x 4-col register
// tile of packed f32x2 accumulators. xs kept [node][q] -> warp-broadcast LDS.
__global__ void __launch_bounds__(256) k_gemm1(const float* __restrict__ x,
                                               const float* __restrict__ Wl,
                                               const float* __restrict__ Wr) {
    __shared__ float2 xs[64][32];   // [node][q]
    __shared__ float2 wT[32][128];  // [q][c] : (W[2q][c], W[2q+1][c])
    int tid = threadIdx.x;
    int nodeBase = blockIdx.x * 64;

    for (int idx = tid; idx < 32 * 128; idx += 256) {
        int q = idx >> 7, c = idx & 127;
        float a, b;
        if (c < 64) { a = Wl[(2 * q) * 64 + c];        b = Wl[(2 * q + 1) * 64 + c]; }
        else        { a = Wr[(2 * q) * 64 + (c - 64)]; b = Wr[(2 * q + 1) * 64 + (c - 64)]; }
        wT[q][c] = make_float2(a, b);
    }
    const float2* xg = (const float2*)x;
    for (int idx = tid; idx < 64 * 32; idx += 256) {
        int node = idx >> 5, q = idx & 31;
        int gn = nodeBase + node;
        if (gn >= N_NODES) gn = N_NODES - 1;
        xs[node][q] = xg[(size_t)gn * 32 + q];
    }
    __syncthreads();

    int tc = tid & 31;   // col group: cols tc*4 .. tc*4+3
    int tn = tid >> 5;   // node group: nodes tn*8 .. tn*8+7

    ull acc[8][4];
    #pragma unroll
    for (int i = 0; i < 8; i++)
        #pragma unroll
        for (int j = 0; j < 4; j++) acc[i][j] = 0;

    #pragma unroll 4
    for (int q = 0; q < 32; q++) {
        ull wv[4], xv[8];
        #pragma unroll
        for (int j = 0; j < 4; j++) wv[j] = *(const ull*)&wT[q][tc * 4 + j];
        #pragma unroll
        for (int i = 0; i < 8; i++) xv[i] = *(const ull*)&xs[tn * 8 + i][q];
        #pragma unroll
        for (int i = 0; i < 8; i++)
            #pragma unroll
            for (int j = 0; j < 4; j++) ffma2(acc[i][j], xv[i], wv[j]);
    }

    #pragma unroll
    for (int i = 0; i < 8; i++) {
        int node = nodeBase + tn * 8 + i;
        if (node < N_NODES) {
            float4 v = make_float4(hadd2(acc[i][0]), hadd2(acc[i][1]),
                                   hadd2(acc[i][2]), hadd2(acc[i][3]));
            ((float4*)(g_XW + (size_t)node * 128))[tc] = v;
        }
    }
}

// ---------------- layer-1 aggregate + bias + normalize + relu ----------------
__global__ void k_agg1(const float* __restrict__ b1) {
    int g = threadIdx.y, t = threadIdx.x;
    int n = blockIdx.x * 4 + g;
    int s0 = g_rowstart[n], s1 = g_rowstart[n + 1];
    float sum = 0.f;
    for (int i = s0; i < s1; i++) {
        int s = g_srcs[i];
        sum += g_XW[(size_t)s * 128 + t];
    }
    float val = sum * g_recip[n] + b1[t] + g_XW[(size_t)n * 128 + 64 + t];
    float sq = val * val;
    #pragma unroll
    for (int off = 16; off > 0; off >>= 1) sq += __shfl_xor_sync(0xffffffffu, sq, off);
    __shared__ float wsum[4][2];
    if ((t & 31) == 0) wsum[g][t >> 5] = sq;
    __syncthreads();
    float ss = wsum[g][0] + wsum[g][1];
    float inv = 1.0f / fmaxf(sqrtf(ss), 1e-12f);
    g_h[(size_t)n * 64 + t] = fmaxf(val * inv, 0.0f);
}

// ---------------- GEMM2: HW[n][0:64] = h[n] @ [W2l | W2r] ----------------
// 64-node x 64-col tile; 128 threads; per-thread 8x4 register tile.
__global__ void __launch_bounds__(128) k_gemm2(const float* __restrict__ W2l,
                                               const float* __restrict__ W2r) {
    __shared__ float2 hs[64][32];  // [node][q]
    __shared__ float2 wT[32][64];  // [q][c]
    int tid = threadIdx.x;
    int nodeBase = blockIdx.x * 64;

    for (int idx = tid; idx < 32 * 64; idx += 128) {
        int q = idx >> 6, c = idx & 63;
        float a, b;
        if (c < 32) { a = W2l[(2 * q) * 32 + c];        b = W2l[(2 * q + 1) * 32 + c]; }
        else        { a = W2r[(2 * q) * 32 + (c - 32)]; b = W2r[(2 * q + 1) * 32 + (c - 32)]; }
        wT[q][c] = make_float2(a, b);
    }
    const float2* hg = (const float2*)g_h;
    for (int idx = tid; idx < 64 * 32; idx += 128) {
        int node = idx >> 5, q = idx & 31;
        int gn = nodeBase + node;
        if (gn >= N_NODES) gn = N_NODES - 1;
        hs[node][q] = hg[(size_t)gn * 32 + q];
    }
    __syncthreads();

    int tc = tid & 15;   // col group: cols tc*4 .. tc*4+3
    int tn = tid >> 4;   // node group: nodes tn*8 .. tn*8+7

    ull acc[8][4];
    #pragma unroll
    for (int i = 0; i < 8; i++)
        #pragma unroll
        for (int j = 0; j < 4; j++) acc[i][j] = 0;

    #pragma unroll 4
    for (int q = 0; q < 32; q++) {
        ull wv[4], xv[8];
        #pragma unroll
        for (int j = 0; j < 4; j++) wv[j] = *(const ull*)&wT[q][tc * 4 + j];
        #pragma unroll
        for (int i = 0; i < 8; i++) xv[i] = *(const ull*)&hs[tn * 8 + i][q];
        #pragma unroll
        for (int i = 0; i < 8; i++)
            #pragma unroll
            for (int j = 0; j < 4; j++) ffma2(acc[i][j], xv[i], wv[j]);
    }

    #pragma unroll
    for (int i = 0; i < 8; i++) {
        int node = nodeBase + tn * 8 + i;
        if (node < N_NODES) {
            float4 v = make_float4(hadd2(acc[i][0]), hadd2(acc[i][1]),
                                   hadd2(acc[i][2]), hadd2(acc[i][3]));
            ((float4*)(g_HW + (size_t)node * 64))[tc] = v;
        }
    }
}

// ---------------- layer-2 aggregate + bias + normalize ----------------
__global__ void k_agg2(const float* __restrict__ b2, float* __restrict__ out) {
    int g = threadIdx.y, t = threadIdx.x;
    int n = blockIdx.x * 8 + g;
    int s0 = g_rowstart[n], s1 = g_rowstart[n + 1];
    float sum = 0.f;
    for (int i = s0; i < s1; i++) {
        int s = g_srcs[i];
        sum += g_HW[(size_t)s * 64 + t];
    }
    float val = sum * g_recip[n] + b2[t] + g_HW[(size_t)n * 64 + 32 + t];
    float sq = val * val;
    #pragma unroll
    for (int off = 16; off > 0; off >>= 1) sq += __shfl_xor_sync(0xffffffffu, sq, off);
    float inv = 1.0f / fmaxf(sqrtf(sq), 1e-12f);
    out[(size_t)n * 32 + t] = val * inv;
}

// ---------------- launch ----------------
extern "C" void kernel_launch(void* const* d_in, const int* in_sizes, int n_in,
                              void* d_out, int out_size) {
    const float* x   = (const float*)d_in[0];
    const void*  ei  = d_in[1];  // int64 or int32, detected on device
    const float* W1l = (const float*)d_in[2];
    const float* b1  = (const float*)d_in[3];
    const float* W1r = (const float*)d_in[4];
    const float* W2l = (const float*)d_in[5];
    const float* b2  = (const float*)d_in[6];
    const float* W2r = (const float*)d_in[7];
    float* out = (float*)d_out;

    k_detect<<<1, 32>>>((const int*)ei);
    k_zero_cnt<<<(N_NODES + 255) / 256, 256>>>();
    k_hist<<<1024, 256>>>(ei);
    k_scan1<<<NBLK, SCAN_B>>>();
    k_scan2<<<1, 128>>>();
    k_gemm1<<<GBLK, 256>>>(x, W1l, W1r);   // 6th launch -> ncu profiles this
    k_scan3<<<(N_NODES + 255) / 256, 256>>>();
    k_scatter<<<1024, 256>>>(ei);
    k_agg1<<<N_NODES / 4, dim3(64, 4)>>>(b1);
    k_gemm2<<<GBLK, 128>>>(W2l, W2r);
    k_agg2<<<N_NODES / 8, dim3(32, 8)>>>(b2, out);
}

// round 15
// speedup vs baseline: 1.0614x; 1.0614x over previous
#include <cuda_runtime.h>
#include <cstdint>

#define N_NODES 100000
#define N_EDGES 1000000
#define SCAN_B 1024
#define NBLK ((N_NODES + SCAN_B - 1) / SCAN_B)   // 98
#define GBLK ((N_NODES + 63) / 64)               // 1563 (64-node gemm tiles)

// ---------------- device scratch (static, allocation-free) ----------------
__device__ int   g_cnt[N_NODES];
__device__ int   g_rowstart[N_NODES + 1];
__device__ int   g_cursor[N_NODES];
__device__ float g_recip[N_NODES];
__device__ int   g_srcs[N_EDGES];
__device__ int   g_bsum[NBLK];
__device__ int   g_boff[NBLK];
__device__ float g_XW[(size_t)N_NODES * 128];  // [A=x@W1l | B=x@W1r]
__device__ float g_h [(size_t)N_NODES * 64];   // layer-1 output
__device__ float g_HW[(size_t)N_NODES * 64];   // [C=h@W2l | D=h@W2r]
__device__ int   g_is64;

typedef unsigned long long ull;

__device__ __forceinline__ void ffma2(ull& d, ull a, ull b) {
    asm("fma.rn.f32x2 %0, %1, %2, %0;" : "+l"(d) : "l"(a), "l"(b));
}
__device__ __forceinline__ float hadd2(ull v) {
    float lo, hi;
    asm("mov.b64 {%0, %1}, %2;" : "=f"(lo), "=f"(hi) : "l"(v));
    return lo + hi;
}

// ---------------- dtype detection: int64 vs int32 edge_index ----------------
__global__ void k_detect(const int* __restrict__ ei) {
    if (threadIdx.x == 0 && blockIdx.x == 0) {
        int odd_nonzero = 0;
        for (int i = 0; i < 64; i++)
            if (ei[2 * i + 1] != 0) odd_nonzero++;
        // int64 data: high 32-bit words (odd int32 slots) are all zero.
        g_is64 = (odd_nonzero == 0) ? 1 : 0;
    }
}

__global__ void k_zero_cnt() {
    int i = blockIdx.x * blockDim.x + threadIdx.x;
    if (i < N_NODES) g_cnt[i] = 0;
}

// Vectorized histogram over the dst half of edge_index.
__global__ void k_hist(const void* __restrict__ eiv) {
    int is64 = g_is64;
    int stride = gridDim.x * blockDim.x;
    int tid = blockIdx.x * blockDim.x + threadIdx.x;
    if (is64) {
        const longlong2* dst = (const longlong2*)(((const long long*)eiv) + N_EDGES);
        for (int e = tid; e < N_EDGES / 2; e += stride) {
            longlong2 v = dst[e];
            atomicAdd(&g_cnt[(int)v.x], 1);
            atomicAdd(&g_cnt[(int)v.y], 1);
        }
    } else {
        const int4* dst = (const int4*)(((const int*)eiv) + N_EDGES);
        for (int e = tid; e < N_EDGES / 4; e += stride) {
            int4 v = dst[e];
            atomicAdd(&g_cnt[v.x], 1);
            atomicAdd(&g_cnt[v.y], 1);
            atomicAdd(&g_cnt[v.z], 1);
            atomicAdd(&g_cnt[v.w], 1);
        }
    }
}

// ---------------- hierarchical exclusive scan of g_cnt ----------------
__global__ void __launch_bounds__(SCAN_B) k_scan1() {
    __shared__ int sh[SCAN_B];
    int tid = threadIdx.x;
    int j = blockIdx.x * SCAN_B + tid;
    int c = (j < N_NODES) ? g_cnt[j] : 0;
    int v = c;
    sh[tid] = v;
    __syncthreads();
    #pragma unroll
    for (int off = 1; off < SCAN_B; off <<= 1) {
        int t = (tid >= off) ? sh[tid - off] : 0;
        __syncthreads();
        v += t;
        sh[tid] = v;
        __syncthreads();
    }
    if (j < N_NODES) g_rowstart[j] = v - c;   // local exclusive
    if (tid == SCAN_B - 1) g_bsum[blockIdx.x] = v;
}

__global__ void k_scan2() {
    __shared__ int sh[128];
    int tid = threadIdx.x;
    int c = (tid < NBLK) ? g_bsum[tid] : 0;
    int v = c;
    sh[tid] = v;
    __syncthreads();
    #pragma unroll
    for (int off = 1; off < 128; off <<= 1) {
        int t = (tid >= off) ? sh[tid - off] : 0;
        __syncthreads();
        v += t;
        sh[tid] = v;
        __syncthreads();
    }
    if (tid < NBLK) g_boff[tid] = v - c;      // exclusive block offset
}

__global__ void k_scan3() {
    int j = blockIdx.x * blockDim.x + threadIdx.x;
    if (j < N_NODES) {
        int rs = g_rowstart[j] + g_boff[j >> 10];
        g_rowstart[j] = rs;
        g_cursor[j]   = rs;
        int c = g_cnt[j];
        g_recip[j] = 1.0f / (float)(c > 0 ? c : 1);
    }
    if (j == 0) g_rowstart[N_NODES] = N_EDGES;  // grand total is static
}

__global__ void k_scatter(const void* __restrict__ eiv) {
    int is64 = g_is64;
    int stride = gridDim.x * blockDim.x;
    int tid = blockIdx.x * blockDim.x + threadIdx.x;
    if (is64) {
        const long long* src = (const long long*)eiv;
        const longlong2* dst = (const longlong2*)(src + N_EDGES);
        const longlong2* src2 = (const longlong2*)src;
        for (int e = tid; e < N_EDGES / 2; e += stride) {
            longlong2 d = dst[e];
            longlong2 s = src2[e];
            int p0 = atomicAdd(&g_cursor[(int)d.x], 1);
            g_srcs[p0] = (int)s.x;
            int p1 = atomicAdd(&g_cursor[(int)d.y], 1);
            g_srcs[p1] = (int)s.y;
        }
    } else {
        const int* src = (const int*)eiv;
        const int4* dst = (const int4*)(src + N_EDGES);
        const int4* src4 = (const int4*)src;
        for (int e = tid; e < N_EDGES / 4; e += stride) {
            int4 d = dst[e];
            int4 s = src4[e];
            int p0 = atomicAdd(&g_cursor[d.x], 1); g_srcs[p0] = s.x;
            int p1 = atomicAdd(&g_cursor[d.y], 1); g_srcs[p1] = s.y;
            int p2 = atomicAdd(&g_cursor[d.z], 1); g_srcs[p2] = s.z;
            int p3 = atomicAdd(&g_cursor[d.w], 1); g_srcs[p3] = s.w;
        }
    }
}

// ---------------- GEMM1: XW[n][0:128] = x[n] @ [W1l | W1r] ----------------
// 64-node x 128-col tile; 256 threads; per-thread 8-node x 4-col register tile.
// Thread's columns are {tc + 32j}: wv loads are 32 consecutive float2 per warp
// (conflict-free); xs loads are warp-broadcast. FFMA2-issue bound.
__global__ void __launch_bounds__(256) k_gemm1(const float* __restrict__ x,
                                               const float* __restrict__ Wl,
                                               const float* __restrict__ Wr) {
    __shared__ float2 xs[64][32];   // [node][q]
    __shared__ float2 wT[32][128];  // [q][c] : (W[2q][c], W[2q+1][c])
    int tid = threadIdx.x;
    int nodeBase = blockIdx.x * 64;

    for (int idx = tid; idx < 32 * 128; idx += 256) {
        int q = idx >> 7, c = idx & 127;
        float a, b;
        if (c < 64) { a = Wl[(2 * q) * 64 + c];        b = Wl[(2 * q + 1) * 64 + c]; }
        else        { a = Wr[(2 * q) * 64 + (c - 64)]; b = Wr[(2 * q + 1) * 64 + (c - 64)]; }
        wT[q][c] = make_float2(a, b);
    }
    const float2* xg = (const float2*)x;
    for (int idx = tid; idx < 64 * 32; idx += 256) {
        int node = idx >> 5, q = idx & 31;
        int gn = nodeBase + node;
        if (gn >= N_NODES) gn = N_NODES - 1;
        xs[node][q] = xg[(size_t)gn * 32 + q];
    }
    __syncthreads();

    int tc = tid & 31;   // lane: columns tc, tc+32, tc+64, tc+96
    int tn = tid >> 5;   // node group: nodes tn*8 .. tn*8+7

    ull acc[8][4];
    #pragma unroll
    for (int i = 0; i < 8; i++)
        #pragma unroll
        for (int j = 0; j < 4; j++) acc[i][j] = 0;

    #pragma unroll 4
    for (int q = 0; q < 32; q++) {
        ull wv[4], xv[8];
        #pragma unroll
        for (int j = 0; j < 4; j++) wv[j] = *(const ull*)&wT[q][tc + 32 * j];
        #pragma unroll
        for (int i = 0; i < 8; i++) xv[i] = *(const ull*)&xs[tn * 8 + i][q];
        #pragma unroll
        for (int i = 0; i < 8; i++)
            #pragma unroll
            for (int j = 0; j < 4; j++) ffma2(acc[i][j], xv[i], wv[j]);
    }

    #pragma unroll
    for (int i = 0; i < 8; i++) {
        int node = nodeBase + tn * 8 + i;
        if (node < N_NODES) {
            #pragma unroll
            for (int j = 0; j < 4; j++)
                g_XW[(size_t)node * 128 + tc + 32 * j] = hadd2(acc[i][j]);
        }
    }
}

// ---------------- layer-1 aggregate + bias + normalize + relu ----------------
__global__ void k_agg1(const float* __restrict__ b1) {
    int g = threadIdx.y, t = threadIdx.x;
    int n = blockIdx.x * 4 + g;
    int s0 = g_rowstart[n], s1 = g_rowstart[n + 1];
    float sum = 0.f;
    for (int i = s0; i < s1; i++) {
        int s = g_srcs[i];
        sum += g_XW[(size_t)s * 128 + t];
    }
    float val = sum * g_recip[n] + b1[t] + g_XW[(size_t)n * 128 + 64 + t];
    float sq = val * val;
    #pragma unroll
    for (int off = 16; off > 0; off >>= 1) sq += __shfl_xor_sync(0xffffffffu, sq, off);
    __shared__ float wsum[4][2];
    if ((t & 31) == 0) wsum[g][t >> 5] = sq;
    __syncthreads();
    float ss = wsum[g][0] + wsum[g][1];
    float inv = 1.0f / fmaxf(sqrtf(ss), 1e-12f);
    g_h[(size_t)n * 64 + t] = fmaxf(val * inv, 0.0f);
}

// ---------------- GEMM2: HW[n][0:64] = h[n] @ [W2l | W2r] ----------------
// 64-node x 64-col tile; 128 threads; per-thread 8x4 register tile.
// Thread's columns are {tc + 16j} (tc = tid&15): conflict-free wv loads.
__global__ void __launch_bounds__(128) k_gemm2(const float* __restrict__ W2l,
                                               const float* __restrict__ W2r) {
    __shared__ float2 hs[64][32];  // [node][q]
    __shared__ float2 wT[32][64];  // [q][c]
    int tid = threadIdx.x;
    int nodeBase = blockIdx.x * 64;

    for (int idx = tid; idx < 32 * 64; idx += 128) {
        int q = idx >> 6, c = idx & 63;
        float a, b;
        if (c < 32) { a = W2l[(2 * q) * 32 + c];        b = W2l[(2 * q + 1) * 32 + c]; }
        else        { a = W2r[(2 * q) * 32 + (c - 32)]; b = W2r[(2 * q + 1) * 32 + (c - 32)]; }
        wT[q][c] = make_float2(a, b);
    }
    const float2* hg = (const float2*)g_h;
    for (int idx = tid; idx < 64 * 32; idx += 128) {
        int node = idx >> 5, q = idx & 31;
        int gn = nodeBase + node;
        if (gn >= N_NODES) gn = N_NODES - 1;
        hs[node][q] = hg[(size_t)gn * 32 + q];
    }
    __syncthreads();

    int tc = tid & 15;   // columns tc, tc+16, tc+32, tc+48
    int tn = tid >> 4;   // node group: nodes tn*8 .. tn*8+7

    ull acc[8][4];
    #pragma unroll
    for (int i = 0; i < 8; i++)
        #pragma unroll
        for (int j = 0; j < 4; j++) acc[i][j] = 0;

    #pragma unroll 4
    for (int q = 0; q < 32; q++) {
        ull wv[4], xv[8];
        #pragma unroll
        for (int j = 0; j < 4; j++) wv[j] = *(const ull*)&wT[q][tc + 16 * j];
        #pragma unroll
        for (int i = 0; i < 8; i++) xv[i] = *(const ull*)&hs[tn * 8 + i][q];
        #pragma unroll
        for (int i = 0; i < 8; i++)
            #pragma unroll
            for (int j = 0; j < 4; j++) ffma2(acc[i][j], xv[i], wv[j]);
    }

    #pragma unroll
    for (int i = 0; i < 8; i++) {
        int node = nodeBase + tn * 8 + i;
        if (node < N_NODES) {
            #pragma unroll
            for (int j = 0; j < 4; j++)
                g_HW[(size_t)node * 64 + tc + 16 * j] = hadd2(acc[i][j]);
        }
    }
}

// ---------------- layer-2 aggregate + bias + normalize ----------------
__global__ void k_agg2(const float* __restrict__ b2, float* __restrict__ out) {
    int g = threadIdx.y, t = threadIdx.x;
    int n = blockIdx.x * 8 + g;
    int s0 = g_rowstart[n], s1 = g_rowstart[n + 1];
    float sum = 0.f;
    for (int i = s0; i < s1; i++) {
        int s = g_srcs[i];
        sum += g_HW[(size_t)s * 64 + t];
    }
    float val = sum * g_recip[n] + b2[t] + g_HW[(size_t)n * 64 + 32 + t];
    float sq = val * val;
    #pragma unroll
    for (int off = 16; off > 0; off >>= 1) sq += __shfl_xor_sync(0xffffffffu, sq, off);
    float inv = 1.0f / fmaxf(sqrtf(sq), 1e-12f);
    out[(size_t)n * 32 + t] = val * inv;
}

// ---------------- launch ----------------
// NOTE: the harness launches 2 kernels before ours; ncu (-s 5 -c 1) profiles
// OUR 4th launch. k_gemm1 is placed 4th so the profile captures it.
extern "C" void kernel_launch(void* const* d_in, const int* in_sizes, int n_in,
                              void* d_out, int out_size) {
    const float* x   = (const float*)d_in[0];
    const void*  ei  = d_in[1];  // int64 or int32, detected on device
    const float* W1l = (const float*)d_in[2];
    const float* b1  = (const float*)d_in[3];
    const float* W1r = (const float*)d_in[4];
    const float* W2l = (const float*)d_in[5];
    const float* b2  = (const float*)d_in[6];
    const float* W2r = (const float*)d_in[7];
    float* out = (float*)d_out;

    k_detect<<<1, 32>>>((const int*)ei);
    k_zero_cnt<<<(N_NODES + 255) / 256, 256>>>();
    k_hist<<<1024, 256>>>(ei);
    k_gemm1<<<GBLK, 256>>>(x, W1l, W1r);   // our 4th launch -> profiled
    k_scan1<<<NBLK, SCAN_B>>>();
    k_scan2<<<1, 128>>>();
    k_scan3<<<(N_NODES + 255) / 256, 256>>>();
    k_scatter<<<1024, 256>>>(ei);
    k_agg1<<<N_NODES / 4, dim3(64, 4)>>>(b1);
    k_gemm2<<<GBLK, 128>>>(W2l, W2r);
    k_agg2<<<N_NODES / 8, dim3(32, 8)>>>(b2, out);
}